// round 13
// baseline (speedup 1.0000x reference)
#include <cuda_runtime.h>
#include <cuda_bf16.h>
#include <math.h>
#include <stdint.h>

#define HW    61440
#define MTILE 128
#define NTHR  512
#define BLKB  20480u

typedef unsigned int u32;

// Pre-split (bf16 hi/lo) weights as k32-sliced images, row stride 80 B (16-aligned).
// Per layer: [hi: K/32 slices][lo: K/32 slices], slice = N rows x 80 B.
// Layer bytes = K*N*5 (all multiples of 20480). Bases: L0 0, L1 20480, L2 40960,
// L3 122880, L4 450560, L5 778240, end 860160 = 42 blocks. +2 pad blocks.
__device__ __align__(16) unsigned char g_wb[901120];

// smem layout (bytes):
//   0       A_hi image (128 x 264 halves = 67584)
//   67584   A_lo image (67584)
//   135168  W ring: 3 x 20480 = 61440
//   196608  bias[960]
#define ALO_OFF 67584
#define SM_W    135168
#define SM_BIAS 196608
#define SM_TOT  200448

__device__ __forceinline__ u32 smem_u32(const void* p) {
    u32 a; asm("{ .reg .u64 t; cvta.to.shared.u64 t, %1; cvt.u32.u64 %0, t; }"
               : "=r"(a) : "l"(p)); return a;
}
__device__ __forceinline__ void ldsm4(unsigned* r, u32 addr) {
    asm volatile("ldmatrix.sync.aligned.m8n8.x4.shared.b16 {%0,%1,%2,%3}, [%4];"
        : "=r"(r[0]), "=r"(r[1]), "=r"(r[2]), "=r"(r[3]) : "r"(addr));
}
__device__ __forceinline__ void mma_bf16(float* d, const unsigned* a, unsigned b0, unsigned b1) {
    asm volatile("mma.sync.aligned.m16n8k16.row.col.f32.bf16.bf16.f32 "
        "{%0,%1,%2,%3}, {%4,%5,%6,%7}, {%8,%9}, {%0,%1,%2,%3};"
        : "+f"(d[0]), "+f"(d[1]), "+f"(d[2]), "+f"(d[3])
        : "r"(a[0]), "r"(a[1]), "r"(a[2]), "r"(a[3]), "r"(b0), "r"(b1));
}
__device__ __forceinline__ void cp16(u32 dst, const void* src) {
    asm volatile("cp.async.cg.shared.global [%0], [%1], 16;" :: "r"(dst), "l"(src));
}
#define CP_COMMIT() asm volatile("cp.async.commit_group;" ::: "memory")
#define CP_WAIT1()  asm volatile("cp.async.wait_group 1;" ::: "memory")
#define CP_WAIT0()  asm volatile("cp.async.wait_group 0;" ::: "memory")

__device__ __forceinline__ u32 pack_bf2(float v0, float v1) {
    __nv_bfloat162 h = __floats2bfloat162_rn(v0, v1);
    return *(u32*)&h;
}

// ---------- weight prep (identical layout to proven R11 kernel) ----------
__global__ void prep_weights(
    const float* __restrict__ w0, const float* __restrict__ w1,
    const float* __restrict__ w2, const float* __restrict__ w3,
    const float* __restrict__ w4, const float* __restrict__ w5)
{
    int i = blockIdx.x * blockDim.x + threadIdx.x;
    if (i >= 172032) return;
    const float* w; int j, K, N, ldw; u32 base;
    if      (i < 4096)   { j = i;          w = w0; K = 64;  N = 64;  ldw = 65;  base = 0; }
    else if (i < 8192)   { j = i - 4096;   w = w1; K = 64;  N = 64;  ldw = 64;  base = 20480; }
    else if (i < 24576)  { j = i - 8192;   w = w2; K = 64;  N = 256; ldw = 64;  base = 40960; }
    else if (i < 90112)  { j = i - 24576;  w = w3; K = 256; N = 256; ldw = 256; base = 122880; }
    else if (i < 155648) { j = i - 90112;  w = w4; K = 256; N = 256; ldw = 256; base = 450560; }
    else                 { j = i - 155648; w = w5; K = 256; N = 64;  ldw = 256; base = 778240; }
    int n = j / K, k = j % K;
    float v = w[n * ldw + k];
    __nv_bfloat16 h = __float2bfloat16(v);
    __nv_bfloat16 lo = __float2bfloat16(v - __bfloat162float(h));
    u32 half_img = (u32)(K / 32) * (u32)N * 80u;
    u32 dst = base + (u32)(k >> 5) * ((u32)N * 80u) + (u32)n * 80u + (u32)(k & 31) * 2u;
    *(__nv_bfloat16*)(g_wb + dst)            = h;
    *(__nv_bfloat16*)(g_wb + dst + half_img) = lo;
}

// ---------- per-layer GEMM over k32 slices; 3-deep block ring ----------
// D[128 x N] = A[128 x K] @ W^T, 3-term bf16 split, in-place activation update.
// 16 warps: m0=(wid&3)*32; n0=(wid>>2)*(N/4).
template<int K, int N, bool SIN, bool LAST>
__device__ __forceinline__ void layer_mma(
    unsigned char* smem, u32 sb, u32 wbase, const float* bias_l, int tid)
{
    constexpr int Sin = K + 8;     // halves
    constexpr int Sout = N + 8;
    constexpr int NC  = N / 64;    // n16 chunks per warp
    constexpr int CH2 = K / 32;    // slices per image (hi or lo)
    constexpr int SLB = N * 80;    // slice bytes

    const int lane = tid & 31, wid = tid >> 5;
    const int m0 = (wid & 3) * 32;
    const int n0 = (wid >> 2) * (N / 4);

    float acc[2][N / 32][4];
    #pragma unroll
    for (int mt = 0; mt < 2; ++mt)
        #pragma unroll
        for (int j = 0; j < N / 32; ++j)
            #pragma unroll
            for (int q = 0; q < 4; ++q) acc[mt][j][q] = 0.0f;

    const int koff8 = (lane & 16) ? 8 : 0;
    const u32 AHI = sb;
    const u32 ALO = sb + ALO_OFF;
    const u32 aoff = (u32)(((m0 + (lane & 15)) * Sin + koff8) * 2);
    const u32 boff = (u32)(((n0 + (lane & 15)) * 40 + koff8) * 2);

    #pragma unroll 1
    for (int s = 0; s < 2 * CH2; ++s) {
        const u32 goff = wbase + (u32)s * SLB;
        if (goff % BLKB == 0) {
            // block boundary: rotate ring, prefetch 2 blocks ahead
            __syncthreads();
            CP_WAIT1();
            const u32 pfb = goff / BLKB + 2;   // pad blocks make this always safe
            const unsigned char* src = g_wb + (size_t)pfb * BLKB;
            const u32 dst = sb + SM_W + (pfb % 3u) * BLKB;
            for (int i = tid * 16; i < (int)BLKB; i += NTHR * 16)
                cp16(dst + i, src + i);
            CP_COMMIT();
        }
        const u32 WB = sb + SM_W + ((goff / BLKB) % 3u) * BLKB + (goff % BLKB);
        const int c = (s < CH2) ? s : s - CH2;

        if (s < CH2) {
            // hi slice: acc += Ah*Bh + Al*Bh
            #pragma unroll
            for (int kk = 0; kk < 2; ++kk) {
                const int kg = c * 2 + kk;
                unsigned ah[2][4], al[2][4], bh[NC][4];
                ldsm4(ah[0], AHI + aoff + kg * 32);
                ldsm4(ah[1], AHI + aoff + 16 * Sin * 2 + kg * 32);
                ldsm4(al[0], ALO + aoff + kg * 32);
                ldsm4(al[1], ALO + aoff + 16 * Sin * 2 + kg * 32);
                #pragma unroll
                for (int nc = 0; nc < NC; ++nc)
                    ldsm4(bh[nc], WB + boff + nc * (16 * 80) + kk * 32);
                #pragma unroll
                for (int nc = 0; nc < NC; ++nc)
                    #pragma unroll
                    for (int mt = 0; mt < 2; ++mt) {
                        mma_bf16(acc[mt][nc * 2 + 0], ah[mt], bh[nc][0], bh[nc][2]);
                        mma_bf16(acc[mt][nc * 2 + 1], ah[mt], bh[nc][1], bh[nc][3]);
                    }
                #pragma unroll
                for (int nc = 0; nc < NC; ++nc)
                    #pragma unroll
                    for (int mt = 0; mt < 2; ++mt) {
                        mma_bf16(acc[mt][nc * 2 + 0], al[mt], bh[nc][0], bh[nc][2]);
                        mma_bf16(acc[mt][nc * 2 + 1], al[mt], bh[nc][1], bh[nc][3]);
                    }
            }
        } else {
            // lo slice: acc += Ah*Bl
            #pragma unroll
            for (int kk = 0; kk < 2; ++kk) {
                const int kg = c * 2 + kk;
                unsigned ah[2][4], bl[NC][4];
                ldsm4(ah[0], AHI + aoff + kg * 32);
                ldsm4(ah[1], AHI + aoff + 16 * Sin * 2 + kg * 32);
                #pragma unroll
                for (int nc = 0; nc < NC; ++nc)
                    ldsm4(bl[nc], WB + boff + nc * (16 * 80) + kk * 32);
                #pragma unroll
                for (int nc = 0; nc < NC; ++nc)
                    #pragma unroll
                    for (int mt = 0; mt < 2; ++mt) {
                        mma_bf16(acc[mt][nc * 2 + 0], ah[mt], bl[nc][0], bl[nc][2]);
                        mma_bf16(acc[mt][nc * 2 + 1], ah[mt], bl[nc][1], bl[nc][3]);
                    }
            }
        }
    }
    __syncthreads();   // all MMAs done before in-place writeback

    const int r = lane >> 2, cq = lane & 3;
    #pragma unroll
    for (int mt = 0; mt < 2; ++mt) {
        #pragma unroll
        for (int j = 0; j < N / 32; ++j) {
            const int col = n0 + j * 8 + cq * 2;
            const float b0v = bias_l[col], b1v = bias_l[col + 1];
            const int row0 = m0 + mt * 16 + r;
            float v00 = acc[mt][j][0] + b0v, v01 = acc[mt][j][1] + b1v;
            float v10 = acc[mt][j][2] + b0v, v11 = acc[mt][j][3] + b1v;
            if constexpr (SIN) {
                v00 = sinf(30.0f * v00); v01 = sinf(30.0f * v01);
                v10 = sinf(30.0f * v10); v11 = sinf(30.0f * v11);
            }
            if constexpr (!LAST) {
                __nv_bfloat162 h0 = __floats2bfloat162_rn(v00, v01);
                __nv_bfloat162 h1 = __floats2bfloat162_rn(v10, v11);
                float l00 = v00 - __bfloat162float(__low2bfloat16(h0));
                float l01 = v01 - __bfloat162float(__high2bfloat16(h0));
                float l10 = v10 - __bfloat162float(__low2bfloat16(h1));
                float l11 = v11 - __bfloat162float(__high2bfloat16(h1));
                *(u32*)(smem + 2 * (row0 * Sout + col))                 = *(u32*)&h0;
                *(u32*)(smem + 2 * ((row0 + 8) * Sout + col))           = *(u32*)&h1;
                *(u32*)(smem + ALO_OFF + 2 * (row0 * Sout + col))       = pack_bf2(l00, l01);
                *(u32*)(smem + ALO_OFF + 2 * ((row0 + 8) * Sout + col)) = pack_bf2(l10, l11);
            } else {
                float* smf = (float*)smem;   // [n][128 pixels] fp32
                smf[col * 128 + row0]           = v00;
                smf[(col + 1) * 128 + row0]     = v01;
                smf[col * 128 + row0 + 8]       = v10;
                smf[(col + 1) * 128 + row0 + 8] = v11;
            }
        }
    }
}

extern __shared__ unsigned char smem[];

__global__ __launch_bounds__(NTHR, 1)
void liif_mma_kernel(
    const float* __restrict__ feat, const float* __restrict__ times,
    const float* __restrict__ w0,
    const float* __restrict__ b0, const float* __restrict__ b1,
    const float* __restrict__ b2, const float* __restrict__ b3,
    const float* __restrict__ b4, const float* __restrict__ b5,
    float* __restrict__ out)
{
    const int tid = threadIdx.x;
    const int p0 = blockIdx.x * MTILE;
    const int bb = blockIdx.y;
    const int tt = blockIdx.z;
    const u32 sb = smem_u32(smem);
    const float tval = times[tt];

    // prologue: prefetch blocks 0 and 1 into ring slots 0 and 1 (separate groups)
    for (int i = tid * 16; i < (int)BLKB; i += NTHR * 16)
        cp16(sb + SM_W + i, g_wb + i);
    CP_COMMIT();
    for (int i = tid * 16; i < (int)BLKB; i += NTHR * 16)
        cp16(sb + SM_W + BLKB + i, g_wb + BLKB + i);
    CP_COMMIT();

    // biases (time folded into b0)
    float* sbias = (float*)(smem + SM_BIAS);
    for (int i = tid; i < 960; i += NTHR) {
        float v;
        if      (i < 64)  v = b0[i] + tval * w0[i * 65 + 64];
        else if (i < 128) v = b1[i - 64];
        else if (i < 384) v = b2[i - 128];
        else if (i < 640) v = b3[i - 384];
        else if (i < 896) v = b4[i - 640];
        else              v = b5[i - 896];
        sbias[i] = v;
    }

    // feat -> A hi/lo images, stride 72 halves (identity gather)
    for (int e = tid; e < MTILE * 64; e += NTHR) {
        int c = e >> 7, p = e & 127;
        float v = feat[(size_t)(bb * 64 + c) * HW + p0 + p];
        __nv_bfloat16 h = __float2bfloat16(v);
        __nv_bfloat16 lo = __float2bfloat16(v - __bfloat162float(h));
        *(__nv_bfloat16*)(smem + 2 * (p * 72 + c))           = h;
        *(__nv_bfloat16*)(smem + ALO_OFF + 2 * (p * 72 + c)) = lo;
    }
    // (first block boundary inside L0 does sync + wait)

    //                K    N   SIN    LAST
    layer_mma< 64,  64, true,  false>(smem, sb, 0,      sbias,       tid);
    layer_mma< 64,  64, true,  false>(smem, sb, 20480,  sbias + 64,  tid);
    layer_mma< 64, 256, true,  false>(smem, sb, 40960,  sbias + 128, tid);
    layer_mma<256, 256, true,  false>(smem, sb, 122880, sbias + 384, tid);
    layer_mma<256, 256, true,  false>(smem, sb, 450560, sbias + 640, tid);
    layer_mma<256,  64, false, true >(smem, sb, 778240, sbias + 896, tid);

    CP_WAIT0();        // drain leftover pad prefetches before exit path
    __syncthreads();
    // coalesced store: out[(tt*2+bb)*64 + n][p0 + p]
    float* smf = (float*)smem;
    float* gout = out + (size_t)(tt * 2 + bb) * 64 * HW;
    for (int e = tid; e < 64 * MTILE; e += NTHR) {
        int n = e >> 7, p = e & 127;
        gout[(size_t)n * HW + p0 + p] = smf[n * 128 + p];
    }
}

extern "C" void kernel_launch(void* const* d_in, const int* in_sizes, int n_in,
                              void* d_out, int out_size) {
    const float* feat  = (const float*)d_in[0];
    const float* times = (const float*)d_in[1];
    const float* w0 = (const float*)d_in[2];
    const float* b0 = (const float*)d_in[3];
    const float* w1 = (const float*)d_in[4];
    const float* b1 = (const float*)d_in[5];
    const float* w2 = (const float*)d_in[6];
    const float* b2 = (const float*)d_in[7];
    const float* w3 = (const float*)d_in[8];
    const float* b3 = (const float*)d_in[9];
    const float* w4 = (const float*)d_in[10];
    const float* b4 = (const float*)d_in[11];
    const float* w5 = (const float*)d_in[12];
    const float* b5 = (const float*)d_in[13];
    float* out = (float*)d_out;

    prep_weights<<<(172032 + 255) / 256, 256>>>(w0, w1, w2, w3, w4, w5);

    cudaFuncSetAttribute(liif_mma_kernel,
                         cudaFuncAttributeMaxDynamicSharedMemorySize, SM_TOT);
    dim3 grid(HW / MTILE, 2, 3);   // 480 x 2 x 3 = 2880 CTAs
    liif_mma_kernel<<<grid, NTHR, SM_TOT>>>(
        feat, times, w0, b0, b1, b2, b3, b4, b5, out);
}